// round 1
// baseline (speedup 1.0000x reference)
#include <cuda_runtime.h>
#include <math.h>

// Problem constants
#define BATCH 2048
#define TSEQ  256
#define FIN   64
#define NT    256          // threads per block
#define ROWS  16           // batch rows per block
#define NBLK  (BATCH/ROWS) // 128
#define STR   20           // padded row stride (floats) in state buffers (bank-friendly, 16B-aligned)

// Shared memory layout (float offsets)
#define WP0_N   (128*64*4)            // layer0 weights [k=128][u=64][g=4]
#define WP1_N   (96*32*4)             // layer1 [k=96][u=32][g=4]
#define WP2_N   (48*16*4)             // layer2 [k=48][u=16][g=4]
#define WP0_OFF 0
#define WP1_OFF (WP0_OFF + WP0_N)     // 32768
#define WP2_OFF (WP1_OFF + WP1_N)     // 45056
#define BP0_OFF (WP2_OFF + WP2_N)     // 48128   (64u x 4g)
#define BP1_OFF (BP0_OFF + 256)       // 48384   (32u x 4g)
#define BP2_OFF (BP1_OFF + 128)       // 48512   (16u x 4g)
#define WDS_OFF (BP2_OFF + 64)        // 48576
#define BDS_OFF (WDS_OFF + 16)        // 48592
#define IN0_OFF (BDS_OFF + 4)         // 48596 (div by 4 -> 16B aligned)
#define IN1_OFF (IN0_OFF + 128*STR)   // 51156
#define IN2_OFF (IN1_OFF + 96*STR)    // 53076
#define SMEM_FLOATS (IN2_OFF + 48*STR) // 54036
#define SMEM_BYTES  (SMEM_FLOATS * 4)  // 216144

__device__ __forceinline__ float sigf(float x) {
    // 1/(1+e^-x), safe at extremes: expf(+inf)->inf -> 0 ; expf(-inf)->0 -> 1
    return __fdividef(1.0f, 1.0f + __expf(-x));
}
__device__ __forceinline__ float tanhe(float x) {
    // tanh(x) = 2*sigmoid(2x) - 1, NaN-free at extremes
    return 2.0f * __fdividef(1.0f, 1.0f + __expf(-2.0f * x)) - 1.0f;
}

__global__ void __launch_bounds__(NT, 1) lstm3_fused_kernel(
    const float* __restrict__ x,
    const float* __restrict__ W0, const float* __restrict__ U0, const float* __restrict__ b0,
    const float* __restrict__ W1, const float* __restrict__ U1, const float* __restrict__ b1,
    const float* __restrict__ W2, const float* __restrict__ U2, const float* __restrict__ b2,
    const float* __restrict__ Wd, const float* __restrict__ bd,
    float* __restrict__ out)
{
    extern __shared__ float sm[];
    const int tid  = threadIdx.x;
    const int row0 = blockIdx.x * ROWS;

    float* wp0 = sm + WP0_OFF;
    float* wp1 = sm + WP1_OFF;
    float* wp2 = sm + WP2_OFF;
    float* bp0 = sm + BP0_OFF;
    float* bp1 = sm + BP1_OFF;
    float* bp2 = sm + BP2_OFF;
    float* wds = sm + WDS_OFF;
    float* bds = sm + BDS_OFF;
    float* in0 = sm + IN0_OFF;   // [k=128][r(STR)] : k<64 x_t, k>=64 h0
    float* in1 = sm + IN1_OFF;   // [k=96][r]       : k<64 h0^t, k>=64 h1
    float* in2 = sm + IN2_OFF;   // [k=48][r]       : k<32 h1^t, k>=32 h2

    // ---- load + rearrange weights: [k][u][g], k = concat(input-dim, hidden-dim) ----
    for (int idx = tid; idx < WP0_N; idx += NT) {
        int g = idx & 3, u = (idx >> 2) & 63, k = idx >> 8;
        wp0[idx] = (k < 64) ? W0[k*256 + g*64 + u] : U0[(k-64)*256 + g*64 + u];
    }
    for (int idx = tid; idx < WP1_N; idx += NT) {
        int g = idx & 3, u = (idx >> 2) & 31, k = idx >> 7;
        wp1[idx] = (k < 64) ? W1[k*128 + g*32 + u] : U1[(k-64)*128 + g*32 + u];
    }
    for (int idx = tid; idx < WP2_N; idx += NT) {
        int g = idx & 3, u = (idx >> 2) & 15, k = idx >> 6;
        wp2[idx] = (k < 32) ? W2[k*64 + g*16 + u] : U2[(k-32)*64 + g*16 + u];
    }
    if (tid < 256) bp0[tid] = b0[(tid & 3)*64 + (tid >> 2)];
    if (tid < 128) bp1[tid] = b1[(tid & 3)*32 + (tid >> 2)];
    if (tid < 64)  bp2[tid] = b2[(tid & 3)*16 + (tid >> 2)];
    if (tid < 16)  wds[tid] = Wd[tid];
    if (tid == 0)  bds[0]   = bd[0];
    // zero recurrent-state parts (h at t=-1 is 0)
    for (int idx = tid; idx < 64*STR; idx += NT) in0[64*STR + idx] = 0.0f;
    for (int idx = tid; idx < 32*STR; idx += NT) in1[64*STR + idx] = 0.0f;
    for (int idx = tid; idx < 16*STR; idx += NT) in2[32*STR + idx] = 0.0f;
    __syncthreads();

    // thread mappings
    const int u0 = tid & 63, rg0 = tid >> 6;   // 64 units x 4 row-groups (4 rows each)
    const int u1 = tid & 31, rg1 = tid >> 5;   // 32 units x 8 row-groups (2 rows each)
    const int u2 = tid & 15, r2  = tid >> 4;   // 16 units x 16 rows (1 row each)

    const float4 bias0 = *reinterpret_cast<const float4*>(bp0 + u0*4);
    const float4 bias1 = *reinterpret_cast<const float4*>(bp1 + u1*4);
    const float4 bias2 = *reinterpret_cast<const float4*>(bp2 + u2*4);

    float c0[4] = {0.f, 0.f, 0.f, 0.f};
    float c1[2] = {0.f, 0.f};
    float c2v   = 0.f;

    // x staging (software pipelined one step ahead)
    const int f0 = tid & 63;
    const int ra = tid >> 6;
    float xr[4];
#pragma unroll
    for (int j = 0; j < 4; ++j)
        xr[j] = x[(size_t)(row0 + ra + 4*j) * (TSEQ * FIN) + f0];

    const float4* wp0v = reinterpret_cast<const float4*>(wp0);
    const float4* wp1v = reinterpret_cast<const float4*>(wp1);
    const float4* wp2v = reinterpret_cast<const float4*>(wp2);

    for (int t = 0; t < TSEQ; ++t) {
        // stage x_t into in0 (k<64)
#pragma unroll
        for (int j = 0; j < 4; ++j)
            in0[f0*STR + ra + 4*j] = xr[j];
        __syncthreads();

        // prefetch x_{t+1} (latency hidden behind layer compute)
        if (t + 1 < TSEQ) {
#pragma unroll
            for (int j = 0; j < 4; ++j)
                xr[j] = x[(size_t)(row0 + ra + 4*j) * (TSEQ * FIN) + (size_t)(t+1)*FIN + f0];
        }

        // ---------------- Layer 0 : K=128, H=64, 4 rows/thread ----------------
        float4 acc0[4];
#pragma unroll
        for (int r = 0; r < 4; ++r) acc0[r] = bias0;
        {
            const float4* wc = wp0v + u0;       // stride 64 float4 per k
            const float*  hb = in0 + rg0*4;
#pragma unroll 4
            for (int k = 0; k < 128; ++k) {
                float4 w = wc[k*64];
                float4 h = *reinterpret_cast<const float4*>(hb + k*STR);
                acc0[0].x += h.x*w.x; acc0[0].y += h.x*w.y; acc0[0].z += h.x*w.z; acc0[0].w += h.x*w.w;
                acc0[1].x += h.y*w.x; acc0[1].y += h.y*w.y; acc0[1].z += h.y*w.z; acc0[1].w += h.y*w.w;
                acc0[2].x += h.z*w.x; acc0[2].y += h.z*w.y; acc0[2].z += h.z*w.z; acc0[2].w += h.z*w.w;
                acc0[3].x += h.w*w.x; acc0[3].y += h.w*w.y; acc0[3].z += h.w*w.z; acc0[3].w += h.w*w.w;
            }
        }
        float h0v[4];
#pragma unroll
        for (int r = 0; r < 4; ++r) {
            float ig = sigf(acc0[r].x);
            float fg = sigf(acc0[r].y);
            float gg = tanhe(acc0[r].z);
            float og = sigf(acc0[r].w);
            c0[r]  = fg * c0[r] + ig * gg;
            h0v[r] = og * tanhe(c0[r]);
        }
        __syncthreads();  // all reads of in0 done
        {
            float4 hv = make_float4(h0v[0], h0v[1], h0v[2], h0v[3]);
            *reinterpret_cast<float4*>(in0 + (64 + u0)*STR + rg0*4) = hv;  // recurrent input next step
            *reinterpret_cast<float4*>(in1 + u0*STR        + rg0*4) = hv;  // layer1 input this step
        }
        __syncthreads();

        // ---------------- Layer 1 : K=96, H=32, 2 rows/thread ----------------
        float4 acc1[2];
        acc1[0] = bias1; acc1[1] = bias1;
        {
            const float4* wc = wp1v + u1;       // stride 32 float4 per k
            const float*  hb = in1 + rg1*2;
#pragma unroll 4
            for (int k = 0; k < 96; ++k) {
                float4 w = wc[k*32];
                float2 h = *reinterpret_cast<const float2*>(hb + k*STR);
                acc1[0].x += h.x*w.x; acc1[0].y += h.x*w.y; acc1[0].z += h.x*w.z; acc1[0].w += h.x*w.w;
                acc1[1].x += h.y*w.x; acc1[1].y += h.y*w.y; acc1[1].z += h.y*w.z; acc1[1].w += h.y*w.w;
            }
        }
        float h1v[2];
#pragma unroll
        for (int r = 0; r < 2; ++r) {
            float ig = sigf(acc1[r].x);
            float fg = sigf(acc1[r].y);
            float gg = tanhe(acc1[r].z);
            float og = sigf(acc1[r].w);
            c1[r]  = fg * c1[r] + ig * gg;
            h1v[r] = og * tanhe(c1[r]);
        }
        __syncthreads();
        {
            float2 hv = make_float2(h1v[0], h1v[1]);
            *reinterpret_cast<float2*>(in1 + (64 + u1)*STR + rg1*2) = hv;
            *reinterpret_cast<float2*>(in2 + u1*STR        + rg1*2) = hv;
        }
        __syncthreads();

        // ---------------- Layer 2 : K=48, H=16, 1 row/thread ----------------
        float4 acc2 = bias2;
        {
            const float4* wc = wp2v + u2;       // stride 16 float4 per k
            const float*  hb = in2 + r2;
#pragma unroll 4
            for (int k = 0; k < 48; ++k) {
                float4 w = wc[k*16];
                float  h = hb[k*STR];
                acc2.x += h*w.x; acc2.y += h*w.y; acc2.z += h*w.z; acc2.w += h*w.w;
            }
        }
        float h2val;
        {
            float ig = sigf(acc2.x);
            float fg = sigf(acc2.y);
            float gg = tanhe(acc2.z);
            float og = sigf(acc2.w);
            c2v   = fg * c2v + ig * gg;
            h2val = og * tanhe(c2v);
        }
        __syncthreads();  // all reads of in2 done
        in2[(32 + u2)*STR + r2] = h2val;
        __syncthreads();
    }

    // ---- Dense head: out[r] = h2_last[r] . Wd + bd ----
    if (tid < 16) {
        float s = bds[0];
#pragma unroll
        for (int j = 0; j < 16; ++j)
            s += in2[(32 + j)*STR + tid] * wds[j];
        out[row0 + tid] = s;
    }
}

extern "C" void kernel_launch(void* const* d_in, const int* in_sizes, int n_in,
                              void* d_out, int out_size)
{
    (void)in_sizes; (void)n_in; (void)out_size;
    const float* x  = (const float*)d_in[0];
    const float* W0 = (const float*)d_in[1];
    const float* U0 = (const float*)d_in[2];
    const float* b0 = (const float*)d_in[3];
    const float* W1 = (const float*)d_in[4];
    const float* U1 = (const float*)d_in[5];
    const float* b1 = (const float*)d_in[6];
    const float* W2 = (const float*)d_in[7];
    const float* U2 = (const float*)d_in[8];
    const float* b2 = (const float*)d_in[9];
    const float* Wd = (const float*)d_in[10];
    const float* bd = (const float*)d_in[11];
    float* out = (float*)d_out;

    cudaFuncSetAttribute(lstm3_fused_kernel,
                         cudaFuncAttributeMaxDynamicSharedMemorySize, SMEM_BYTES);
    lstm3_fused_kernel<<<NBLK, NT, SMEM_BYTES>>>(
        x, W0, U0, b0, W1, U1, b1, W2, U2, b2, Wd, bd, out);
}